// round 15
// baseline (speedup 1.0000x reference)
#include <cuda_runtime.h>
#include <cuda_fp16.h>
#include <cstdint>

// ---------------------------------------------------------------------------
// GraphAutoencoder (sm_100 base), R15 (= R14 champion + 2-warps-per-node agg):
//  fork A: memset/hist/scan/sortidx -> aggregate     (index + gather chain)
//  fork 0: prep0 (vectorized) -> x-GEMM (fp16 P)     (tensor chain)
//  join -> n-GEMM (P + bias, relu, emits h) -> decoder GEMM.
// ---------------------------------------------------------------------------

#define N_NODES_MAX 50000
#define N_EDGES_MAX 1000000
#define IN_DIM      256
#define HID_DIM     512
#define OUT_DIM     256
#define KDIM        512          // row stride of g_eA

// ------------------------------ scratch ------------------------------------
__device__ int g_cnt[N_NODES_MAX];
__device__ int g_offs[N_NODES_MAX + 1];
__device__ int g_cur[N_NODES_MAX];
__device__ int g_srt[N_EDGES_MAX];
__device__ __align__(16) __half g_eA[N_NODES_MAX * KDIM];     // [x | nmean]
__device__ __align__(16) __half g_hf[N_NODES_MAX * HID_DIM];  // h fp16
__device__ __align__(16) __half g_P[N_NODES_MAX * HID_DIM];   // x@Wself partial
__device__ __align__(16) __half g_Benc[KDIM * HID_DIM];       // [Wself; Wneigh]
__device__ __align__(16) __half g_Bdec[KDIM * OUT_DIM];
__device__ __align__(16) float g_hfb[N_NODES_MAX * HID_DIM];

// --------------------------- asm helpers -----------------------------------
__device__ __forceinline__ uint32_t smem_u32(const void* p) {
    uint32_t a;
    asm("{ .reg .u64 t; cvta.to.shared.u64 t, %1; cvt.u32.u64 %0, t; }"
        : "=r"(a) : "l"(p));
    return a;
}
__device__ __forceinline__ void cp16(uint32_t dst, const void* src, uint32_t srcsize) {
    asm volatile("cp.async.cg.shared.global [%0], [%1], 16, %2;"
                 :: "r"(dst), "l"(src), "r"(srcsize) : "memory");
}
__device__ __forceinline__ void cp_commit() {
    asm volatile("cp.async.commit_group;" ::: "memory");
}
template <int N>
__device__ __forceinline__ void cp_wait() {
    asm volatile("cp.async.wait_group %0;" :: "n"(N) : "memory");
}
#define LDSM_X4(r0, r1, r2, r3, a) \
    asm volatile("ldmatrix.sync.aligned.m8n8.x4.shared.b16 {%0,%1,%2,%3}, [%4];" \
                 : "=r"(r0), "=r"(r1), "=r"(r2), "=r"(r3) : "r"(a))
#define LDSM_X4_T(r0, r1, r2, r3, a) \
    asm volatile("ldmatrix.sync.aligned.m8n8.x4.trans.shared.b16 {%0,%1,%2,%3}, [%4];" \
                 : "=r"(r0), "=r"(r1), "=r"(r2), "=r"(r3) : "r"(a))
#define MMA16816(c, a0, a1, a2, a3, b0, b1) \
    asm volatile("mma.sync.aligned.m16n8k16.row.col.f32.f16.f16.f32 " \
                 "{%0,%1,%2,%3}, {%4,%5,%6,%7}, {%8,%9}, {%0,%1,%2,%3};" \
                 : "+f"((c)[0]), "+f"((c)[1]), "+f"((c)[2]), "+f"((c)[3]) \
                 : "r"(a0), "r"(a1), "r"(a2), "r"(a3), "r"(b0), "r"(b1))

__device__ __forceinline__ uint2 pack4h(__half2 h0, __half2 h1) {
    uint2 u;
    u.x = *reinterpret_cast<uint32_t*>(&h0);
    u.y = *reinterpret_cast<uint32_t*>(&h1);
    return u;
}

// ----------------------------- prep kernels --------------------------------
__global__ void prep0_kernel(const float* __restrict__ x,
                             const float* __restrict__ Wself,
                             const float* __restrict__ Wneigh,
                             const float* __restrict__ Wdec, int M) {
    int i = blockIdx.x * blockDim.x + threadIdx.x;
    int nx4 = M * (IN_DIM / 4);
    if (i < nx4) {
        int r = i >> 6, c4 = (i & 63) * 4;
        float4 v = reinterpret_cast<const float4*>(x)[i];
        *reinterpret_cast<uint2*>(g_eA + (size_t)r * KDIM + c4) =
            pack4h(__floats2half2_rn(v.x, v.y), __floats2half2_rn(v.z, v.w));
        return;
    }
    int j = i - nx4;
    int nbe4 = (KDIM * HID_DIM) / 4;
    if (j < nbe4) {
        int k = j >> 7, n4 = (j & 127) * 4;
        const float* Wrow = (k < 256) ? (Wself + (size_t)k * HID_DIM)
                                      : (Wneigh + (size_t)(k - 256) * HID_DIM);
        float4 v = *reinterpret_cast<const float4*>(Wrow + n4);
        *reinterpret_cast<uint2*>(g_Benc + (size_t)k * HID_DIM + n4) =
            pack4h(__floats2half2_rn(v.x, v.y), __floats2half2_rn(v.z, v.w));
        return;
    }
    j -= nbe4;
    int nbd4 = (KDIM * OUT_DIM) / 4;
    if (j < nbd4) {
        int k = j >> 6, n4 = (j & 63) * 4;
        float4 v = *reinterpret_cast<const float4*>(Wdec + (size_t)k * OUT_DIM + n4);
        *reinterpret_cast<uint2*>(g_Bdec + (size_t)k * OUT_DIM + n4) =
            pack4h(__floats2half2_rn(v.x, v.y), __floats2half2_rn(v.z, v.w));
    }
}

__global__ void hist_kernel(const int* __restrict__ dst, int n_edges) {
    int i = blockIdx.x * blockDim.x + threadIdx.x;
    if (i < n_edges) atomicAdd(&g_cnt[dst[i]], 1);
}

__global__ __launch_bounds__(1024)
void scan_kernel(int M) {
    __shared__ int sums[1024];
    int t = threadIdx.x;
    int chunk = (M + 1023) / 1024;
    int base = t * chunk;
    int s = 0;
    for (int i = 0; i < chunk; i++) {
        int idx = base + i;
        if (idx < M) s += g_cnt[idx];
    }
    sums[t] = s;
    __syncthreads();
    for (int d = 1; d < 1024; d <<= 1) {
        int v = (t >= d) ? sums[t - d] : 0;
        __syncthreads();
        sums[t] += v;
        __syncthreads();
    }
    int prefix = (t == 0) ? 0 : sums[t - 1];
    for (int i = 0; i < chunk; i++) {
        int idx = base + i;
        if (idx < M) {
            g_offs[idx] = prefix;
            g_cur[idx] = prefix;
            prefix += g_cnt[idx];
        }
    }
    if (t == 1023) g_offs[M] = prefix;
}

__global__ void sortidx_kernel(const int* __restrict__ src,
                               const int* __restrict__ dst, int n_edges) {
    int i = blockIdx.x * blockDim.x + threadIdx.x;
    if (i >= n_edges) return;
    int pos = atomicAdd(&g_cur[dst[i]], 1);
    g_srt[pos] = src[i];
}

// TWO warps per node: warp pair splits edge list (even/odd), combine in smem.
// 512 threads/block = 16 warps = 8 nodes/block.
__global__ __launch_bounds__(512)
void aggregate_kernel(int M) {
    __shared__ float s_acc[8][32][8];     // [pair][lane][8 floats]
    int wid = threadIdx.x >> 5;
    int lane = threadIdx.x & 31;
    int pair = wid >> 1;                  // 0..7
    int half = wid & 1;                   // 0 = even edges, 1 = odd edges
    int node = blockIdx.x * 8 + pair;
    if (node >= M) return;
    int beg = g_offs[node], end = g_offs[node + 1];

    float acc[8] = {0.f, 0.f, 0.f, 0.f, 0.f, 0.f, 0.f, 0.f};
    for (int e = beg + half; e < end; e += 2) {
        int s = g_srt[e];
        uint4 v = *reinterpret_cast<const uint4*>(g_eA + (size_t)s * KDIM + lane * 8);
        const __half2* hp = reinterpret_cast<const __half2*>(&v);
#pragma unroll
        for (int q = 0; q < 4; q++) {
            float2 f = __half22float2(hp[q]);
            acc[2 * q + 0] += f.x;
            acc[2 * q + 1] += f.y;
        }
    }

    if (half == 1) {
#pragma unroll
        for (int q = 0; q < 8; q++) s_acc[pair][lane][q] = acc[q];
    }
    __syncthreads();
    if (half == 0) {
        float inv = 1.0f / fmaxf((float)(end - beg), 1.0f);
        __half2 outv[4];
#pragma unroll
        for (int q = 0; q < 4; q++) {
            float v0 = (acc[2 * q + 0] + s_acc[pair][lane][2 * q + 0]) * inv;
            float v1 = (acc[2 * q + 1] + s_acc[pair][lane][2 * q + 1]) * inv;
            outv[q] = __floats2half2_rn(v0, v1);
        }
        *reinterpret_cast<uint4*>(g_eA + (size_t)node * KDIM + 256 + lane * 8) =
            *reinterpret_cast<uint4*>(outv);
    }
}

// ----------------------------- mma GEMM ------------------------------------
// CTA 128x128, 4 warps (2x2, 64x64), BK=32, 4-stage cp.async pipe.
// MODE 0: partial -> fp16 P. MODE 1: P + bias, relu -> fp32 C + fp16 h.
// MODE 2: bias -> fp32 C.
#define A_PITCH 80
#define B_PITCH 272
#define SZA (128 * A_PITCH)
#define SZB (32 * B_PITCH)
#define STAGES 4
#define SMEM_DYN (STAGES * (SZA + SZB))   // 75776 B

template <int NCH, int MODE>
__global__ __launch_bounds__(128, 2)
void gemm_mma(const __half* __restrict__ A,
              const __half* __restrict__ Bp,
              const float* __restrict__ bias,
              const __half* __restrict__ Pin,
              float* __restrict__ C,
              __half* __restrict__ oH,
              int M, int N) {
    extern __shared__ __align__(16) unsigned char smem[];
    uint32_t sA = smem_u32(smem);
    uint32_t sB = sA + STAGES * SZA;

    int tid = threadIdx.x;
    int wid = tid >> 5, lane = tid & 31;
    int wm = wid & 1, wn = wid >> 1;
    int rowBase = blockIdx.y * 128;
    int colBase = blockIdx.x * 128;

    float c[4][8][4];
#pragma unroll
    for (int mf = 0; mf < 4; mf++)
#pragma unroll
        for (int nf = 0; nf < 8; nf++)
#pragma unroll
            for (int q = 0; q < 4; q++) c[mf][nf][q] = 0.f;

    auto load_chunk = [&](int buf, int ch) {
        int k0 = ch * 32;
#pragma unroll
        for (int i = 0; i < 4; i++) {
            int idx = tid + i * 128;
            int r = idx >> 2, cs = idx & 3;
            int grow = rowBase + r;
            int srow = grow < M ? grow : M - 1;
            cp16(sA + buf * SZA + r * A_PITCH + cs * 16,
                 A + (size_t)srow * KDIM + k0 + cs * 8,
                 grow < M ? 16u : 0u);
        }
#pragma unroll
        for (int i = 0; i < 4; i++) {
            int idx = tid + i * 128;
            int r = idx >> 4, cs = idx & 15;
            cp16(sB + buf * SZB + r * B_PITCH + cs * 16,
                 Bp + (size_t)(k0 + r) * N + colBase + cs * 8, 16u);
        }
        cp_commit();
    };

    uint32_t aAddr = sA + (wm * 64 + (lane & 15)) * A_PITCH + (lane >> 4) * 16;
    uint32_t bAddr = sB + (lane & 15) * B_PITCH + wn * 128 + (lane >> 4) * 16;

    load_chunk(0, 0);
    load_chunk(1, 1);
    if (NCH > 2) load_chunk(2, 2);

    for (int ch = 0; ch < NCH; ch++) {
        int buf = ch % STAGES;
        if (ch >= NCH - 2) cp_wait<0>();
        else               cp_wait<2>();
        __syncthreads();
        if (ch + 3 < NCH) load_chunk((ch + 3) % STAGES, ch + 3);

        uint32_t aB = aAddr + buf * SZA;
        uint32_t bB = bAddr + buf * SZB;
#pragma unroll
        for (int kk = 0; kk < 2; kk++) {
            uint32_t a[16];
#pragma unroll
            for (int g = 0; g < 4; g++)
                LDSM_X4(a[4 * g], a[4 * g + 1], a[4 * g + 2], a[4 * g + 3],
                        aB + g * 16 * A_PITCH + kk * 32);
            uint32_t b[16];
#pragma unroll
            for (int p = 0; p < 4; p++)
                LDSM_X4_T(b[4 * p], b[4 * p + 1], b[4 * p + 2], b[4 * p + 3],
                          bB + kk * 16 * B_PITCH + p * 32);
#pragma unroll
            for (int mf = 0; mf < 4; mf++)
#pragma unroll
                for (int nf = 0; nf < 8; nf++) {
                    uint32_t* bp = b + (nf >> 1) * 4 + (nf & 1) * 2;
                    MMA16816(c[mf][nf], a[4 * mf], a[4 * mf + 1],
                             a[4 * mf + 2], a[4 * mf + 3], bp[0], bp[1]);
                }
        }
    }

    int groupID = lane >> 2, tid4 = lane & 3;
#pragma unroll
    for (int mf = 0; mf < 4; mf++) {
        int r0 = rowBase + wm * 64 + mf * 16 + groupID;
#pragma unroll
        for (int nf = 0; nf < 8; nf++) {
            int cb = colBase + wn * 64 + nf * 8 + tid4 * 2;
            float b0 = 0.f, b1 = 0.f;
            if (MODE != 0) { b0 = bias[cb]; b1 = bias[cb + 1]; }
#pragma unroll
            for (int hh = 0; hh < 2; hh++) {
                int r = r0 + hh * 8;
                if (r >= M) continue;
                float v0 = c[mf][nf][2 * hh + 0] + b0;
                float v1 = c[mf][nf][2 * hh + 1] + b1;
                if (MODE == 0) {
                    __half2 pv;
                    pv.x = __float2half(v0);
                    pv.y = __float2half(v1);
                    *reinterpret_cast<__half2*>(oH + (size_t)r * N + cb) = pv;
                } else if (MODE == 1) {
                    __half2 pv = *reinterpret_cast<const __half2*>(
                        Pin + (size_t)r * N + cb);
                    v0 += __half2float(pv.x);
                    v1 += __half2float(pv.y);
                    v0 = fmaxf(v0, 0.f);
                    v1 = fmaxf(v1, 0.f);
                    *reinterpret_cast<float2*>(C + (size_t)r * N + cb) =
                        make_float2(v0, v1);
                    __half2 hv;
                    hv.x = __float2half(v0);
                    hv.y = __float2half(v1);
                    *reinterpret_cast<__half2*>(oH + (size_t)r * N + cb) = hv;
                } else {
                    *reinterpret_cast<float2*>(C + (size_t)r * N + cb) =
                        make_float2(v0, v1);
                }
            }
        }
    }
}

// ------------------------------ launch -------------------------------------
extern "C" void kernel_launch(void* const* d_in, const int* in_sizes, int n_in,
                              void* d_out, int out_size) {
    const float* x       = (const float*)d_in[0];
    const int*   src     = (const int*)d_in[1];
    const int*   dst     = (const int*)d_in[2];
    const float* W_self  = (const float*)d_in[3];
    const float* W_neigh = (const float*)d_in[4];
    const float* b_enc   = (const float*)d_in[5];
    const float* W_dec   = (const float*)d_in[6];
    const float* b_dec   = (const float*)d_in[7];

    int M  = in_sizes[0] / IN_DIM;
    int nE = in_sizes[1];

    float* out = (float*)d_out;
    float* h;
    if (out_size == M * (OUT_DIM + HID_DIM)) {
        h = out + (long long)M * OUT_DIM;
    } else {
        void* p = nullptr;
        cudaGetSymbolAddress(&p, g_hfb);
        h = (float*)p;
    }

    void *p_eA, *p_hf, *p_P, *p_be, *p_bd, *p_cnt;
    cudaGetSymbolAddress(&p_eA, g_eA);
    cudaGetSymbolAddress(&p_hf, g_hf);
    cudaGetSymbolAddress(&p_P, g_P);
    cudaGetSymbolAddress(&p_be, g_Benc);
    cudaGetSymbolAddress(&p_bd, g_Bdec);
    cudaGetSymbolAddress(&p_cnt, g_cnt);

    cudaFuncSetAttribute(gemm_mma<8, 0>,
                         cudaFuncAttributeMaxDynamicSharedMemorySize, SMEM_DYN);
    cudaFuncSetAttribute(gemm_mma<8, 1>,
                         cudaFuncAttributeMaxDynamicSharedMemorySize, SMEM_DYN);
    cudaFuncSetAttribute(gemm_mma<16, 2>,
                         cudaFuncAttributeMaxDynamicSharedMemorySize, SMEM_DYN);

    static cudaStream_t sA = nullptr;
    static cudaEvent_t ev0 = nullptr, evP = nullptr, evA = nullptr;
    if (!sA) {
        cudaStreamCreateWithFlags(&sA, cudaStreamNonBlocking);
        cudaEventCreateWithFlags(&ev0, cudaEventDisableTiming);
        cudaEventCreateWithFlags(&evP, cudaEventDisableTiming);
        cudaEventCreateWithFlags(&evA, cudaEventDisableTiming);
    }

    // ---- fork: streamA = index chain ----
    cudaEventRecord(ev0, 0);
    cudaStreamWaitEvent(sA, ev0, 0);
    cudaMemsetAsync(p_cnt, 0, (size_t)M * sizeof(int), sA);
    hist_kernel<<<(nE + 255) / 256, 256, 0, sA>>>(dst, nE);
    scan_kernel<<<1, 1024, 0, sA>>>(M);
    sortidx_kernel<<<(nE + 255) / 256, 256, 0, sA>>>(src, dst, nE);

    // ---- stream 0: prep (vectorized) ----
    {
        int total = M * (IN_DIM / 4) + (KDIM * HID_DIM) / 4 + (KDIM * OUT_DIM) / 4;
        prep0_kernel<<<(total + 255) / 256, 256>>>(x, W_self, W_neigh, W_dec, M);
    }
    cudaEventRecord(evP, 0);
    cudaStreamWaitEvent(sA, evP, 0);

    // ---- streamA: aggregate (2 warps per node) ----
    aggregate_kernel<<<(M + 7) / 8, 512, 0, sA>>>(M);
    cudaEventRecord(evA, sA);

    // ---- stream 0 (concurrent with aggregate): x-part GEMM -> fp16 P ----
    {
        dim3 grid(HID_DIM / 128, (M + 127) / 128);
        gemm_mma<8, 0><<<grid, 128, SMEM_DYN>>>(
            (const __half*)p_eA, (const __half*)p_be, nullptr, nullptr,
            nullptr, (__half*)p_P, M, HID_DIM);
    }

    // ---- join: n-part GEMM (reads P), then decoder ----
    cudaStreamWaitEvent(0, evA, 0);
    {
        dim3 grid(HID_DIM / 128, (M + 127) / 128);
        gemm_mma<8, 1><<<grid, 128, SMEM_DYN>>>(
            (const __half*)p_eA + 256,
            (const __half*)p_be + (size_t)256 * HID_DIM,
            b_enc, (const __half*)p_P, h, (__half*)p_hf, M, HID_DIM);
    }
    {
        dim3 grid(OUT_DIM / 128, (M + 127) / 128);
        gemm_mma<16, 2><<<grid, 128, SMEM_DYN>>>(
            (const __half*)p_hf, (const __half*)p_bd, b_dec, nullptr,
            out, nullptr, M, OUT_DIM);
    }
}

// round 16
// speedup vs baseline: 1.0339x; 1.0339x over previous
#include <cuda_runtime.h>
#include <cuda_fp16.h>
#include <cstdint>

// ---------------------------------------------------------------------------
// GraphAutoencoder (sm_100 base), R16 = R14 champion (303.1us), restored:
//  fork A: memset/hist/scan/sortidx -> aggregate     (index + gather chain)
//  fork 0: prep0 (vectorized) -> x-GEMM (fp16 P)     (tensor chain)
//  join -> n-GEMM (P + bias, relu, emits h) -> decoder GEMM.
// ---------------------------------------------------------------------------

#define N_NODES_MAX 50000
#define N_EDGES_MAX 1000000
#define IN_DIM      256
#define HID_DIM     512
#define OUT_DIM     256
#define KDIM        512          // row stride of g_eA

// ------------------------------ scratch ------------------------------------
__device__ int g_cnt[N_NODES_MAX];
__device__ int g_offs[N_NODES_MAX + 1];
__device__ int g_cur[N_NODES_MAX];
__device__ int g_srt[N_EDGES_MAX];
__device__ __align__(16) __half g_eA[N_NODES_MAX * KDIM];     // [x | nmean]
__device__ __align__(16) __half g_hf[N_NODES_MAX * HID_DIM];  // h fp16
__device__ __align__(16) __half g_P[N_NODES_MAX * HID_DIM];   // x@Wself partial
__device__ __align__(16) __half g_Benc[KDIM * HID_DIM];       // [Wself; Wneigh]
__device__ __align__(16) __half g_Bdec[KDIM * OUT_DIM];
__device__ __align__(16) float g_hfb[N_NODES_MAX * HID_DIM];

// --------------------------- asm helpers -----------------------------------
__device__ __forceinline__ uint32_t smem_u32(const void* p) {
    uint32_t a;
    asm("{ .reg .u64 t; cvta.to.shared.u64 t, %1; cvt.u32.u64 %0, t; }"
        : "=r"(a) : "l"(p));
    return a;
}
__device__ __forceinline__ void cp16(uint32_t dst, const void* src, uint32_t srcsize) {
    asm volatile("cp.async.cg.shared.global [%0], [%1], 16, %2;"
                 :: "r"(dst), "l"(src), "r"(srcsize) : "memory");
}
__device__ __forceinline__ void cp_commit() {
    asm volatile("cp.async.commit_group;" ::: "memory");
}
template <int N>
__device__ __forceinline__ void cp_wait() {
    asm volatile("cp.async.wait_group %0;" :: "n"(N) : "memory");
}
#define LDSM_X4(r0, r1, r2, r3, a) \
    asm volatile("ldmatrix.sync.aligned.m8n8.x4.shared.b16 {%0,%1,%2,%3}, [%4];" \
                 : "=r"(r0), "=r"(r1), "=r"(r2), "=r"(r3) : "r"(a))
#define LDSM_X4_T(r0, r1, r2, r3, a) \
    asm volatile("ldmatrix.sync.aligned.m8n8.x4.trans.shared.b16 {%0,%1,%2,%3}, [%4];" \
                 : "=r"(r0), "=r"(r1), "=r"(r2), "=r"(r3) : "r"(a))
#define MMA16816(c, a0, a1, a2, a3, b0, b1) \
    asm volatile("mma.sync.aligned.m16n8k16.row.col.f32.f16.f16.f32 " \
                 "{%0,%1,%2,%3}, {%4,%5,%6,%7}, {%8,%9}, {%0,%1,%2,%3};" \
                 : "+f"((c)[0]), "+f"((c)[1]), "+f"((c)[2]), "+f"((c)[3]) \
                 : "r"(a0), "r"(a1), "r"(a2), "r"(a3), "r"(b0), "r"(b1))

__device__ __forceinline__ uint2 pack4h(__half2 h0, __half2 h1) {
    uint2 u;
    u.x = *reinterpret_cast<uint32_t*>(&h0);
    u.y = *reinterpret_cast<uint32_t*>(&h1);
    return u;
}

// ----------------------------- prep kernels --------------------------------
__global__ void prep0_kernel(const float* __restrict__ x,
                             const float* __restrict__ Wself,
                             const float* __restrict__ Wneigh,
                             const float* __restrict__ Wdec, int M) {
    int i = blockIdx.x * blockDim.x + threadIdx.x;
    int nx4 = M * (IN_DIM / 4);
    if (i < nx4) {
        int r = i >> 6, c4 = (i & 63) * 4;
        float4 v = reinterpret_cast<const float4*>(x)[i];
        *reinterpret_cast<uint2*>(g_eA + (size_t)r * KDIM + c4) =
            pack4h(__floats2half2_rn(v.x, v.y), __floats2half2_rn(v.z, v.w));
        return;
    }
    int j = i - nx4;
    int nbe4 = (KDIM * HID_DIM) / 4;
    if (j < nbe4) {
        int k = j >> 7, n4 = (j & 127) * 4;
        const float* Wrow = (k < 256) ? (Wself + (size_t)k * HID_DIM)
                                      : (Wneigh + (size_t)(k - 256) * HID_DIM);
        float4 v = *reinterpret_cast<const float4*>(Wrow + n4);
        *reinterpret_cast<uint2*>(g_Benc + (size_t)k * HID_DIM + n4) =
            pack4h(__floats2half2_rn(v.x, v.y), __floats2half2_rn(v.z, v.w));
        return;
    }
    j -= nbe4;
    int nbd4 = (KDIM * OUT_DIM) / 4;
    if (j < nbd4) {
        int k = j >> 6, n4 = (j & 63) * 4;
        float4 v = *reinterpret_cast<const float4*>(Wdec + (size_t)k * OUT_DIM + n4);
        *reinterpret_cast<uint2*>(g_Bdec + (size_t)k * OUT_DIM + n4) =
            pack4h(__floats2half2_rn(v.x, v.y), __floats2half2_rn(v.z, v.w));
    }
}

__global__ void hist_kernel(const int* __restrict__ dst, int n_edges) {
    int i = blockIdx.x * blockDim.x + threadIdx.x;
    if (i < n_edges) atomicAdd(&g_cnt[dst[i]], 1);
}

__global__ __launch_bounds__(1024)
void scan_kernel(int M) {
    __shared__ int sums[1024];
    int t = threadIdx.x;
    int chunk = (M + 1023) / 1024;
    int base = t * chunk;
    int s = 0;
    for (int i = 0; i < chunk; i++) {
        int idx = base + i;
        if (idx < M) s += g_cnt[idx];
    }
    sums[t] = s;
    __syncthreads();
    for (int d = 1; d < 1024; d <<= 1) {
        int v = (t >= d) ? sums[t - d] : 0;
        __syncthreads();
        sums[t] += v;
        __syncthreads();
    }
    int prefix = (t == 0) ? 0 : sums[t - 1];
    for (int i = 0; i < chunk; i++) {
        int idx = base + i;
        if (idx < M) {
            g_offs[idx] = prefix;
            g_cur[idx] = prefix;
            prefix += g_cnt[idx];
        }
    }
    if (t == 1023) g_offs[M] = prefix;
}

__global__ void sortidx_kernel(const int* __restrict__ src,
                               const int* __restrict__ dst, int n_edges) {
    int i = blockIdx.x * blockDim.x + threadIdx.x;
    if (i >= n_edges) return;
    int pos = atomicAdd(&g_cur[dst[i]], 1);
    g_srt[pos] = src[i];
}

// one warp per node: gather fp16 x rows, fp32 acc, write fp16 mean
__global__ __launch_bounds__(512)
void aggregate_kernel(int M) {
    int wid_in_blk = threadIdx.x >> 5;
    int lane = threadIdx.x & 31;
    int node = blockIdx.x * 16 + wid_in_blk;
    if (node >= M) return;
    int beg = g_offs[node], end = g_offs[node + 1];

    float acc[8] = {0.f, 0.f, 0.f, 0.f, 0.f, 0.f, 0.f, 0.f};
    int e = beg;
    for (; e + 2 <= end; e += 2) {
        int s0 = g_srt[e + 0], s1 = g_srt[e + 1];
        uint4 v0 = *reinterpret_cast<const uint4*>(g_eA + (size_t)s0 * KDIM + lane * 8);
        uint4 v1 = *reinterpret_cast<const uint4*>(g_eA + (size_t)s1 * KDIM + lane * 8);
        const __half2* h0 = reinterpret_cast<const __half2*>(&v0);
        const __half2* h1 = reinterpret_cast<const __half2*>(&v1);
#pragma unroll
        for (int q = 0; q < 4; q++) {
            float2 f0 = __half22float2(h0[q]);
            float2 f1 = __half22float2(h1[q]);
            acc[2 * q + 0] += f0.x + f1.x;
            acc[2 * q + 1] += f0.y + f1.y;
        }
    }
    if (e < end) {
        int s = g_srt[e];
        uint4 v = *reinterpret_cast<const uint4*>(g_eA + (size_t)s * KDIM + lane * 8);
        const __half2* hp = reinterpret_cast<const __half2*>(&v);
#pragma unroll
        for (int q = 0; q < 4; q++) {
            float2 f = __half22float2(hp[q]);
            acc[2 * q + 0] += f.x;
            acc[2 * q + 1] += f.y;
        }
    }
    float inv = 1.0f / fmaxf((float)(end - beg), 1.0f);
    __half2 outv[4];
#pragma unroll
    for (int q = 0; q < 4; q++)
        outv[q] = __floats2half2_rn(acc[2 * q] * inv, acc[2 * q + 1] * inv);
    *reinterpret_cast<uint4*>(g_eA + (size_t)node * KDIM + 256 + lane * 8) =
        *reinterpret_cast<uint4*>(outv);
}

// ----------------------------- mma GEMM ------------------------------------
// CTA 128x128, 4 warps (2x2, 64x64), BK=32, 4-stage cp.async pipe.
// MODE 0: partial -> fp16 P. MODE 1: P + bias, relu -> fp32 C + fp16 h.
// MODE 2: bias -> fp32 C.
#define A_PITCH 80
#define B_PITCH 272
#define SZA (128 * A_PITCH)
#define SZB (32 * B_PITCH)
#define STAGES 4
#define SMEM_DYN (STAGES * (SZA + SZB))   // 75776 B

template <int NCH, int MODE>
__global__ __launch_bounds__(128, 2)
void gemm_mma(const __half* __restrict__ A,
              const __half* __restrict__ Bp,
              const float* __restrict__ bias,
              const __half* __restrict__ Pin,
              float* __restrict__ C,
              __half* __restrict__ oH,
              int M, int N) {
    extern __shared__ __align__(16) unsigned char smem[];
    uint32_t sA = smem_u32(smem);
    uint32_t sB = sA + STAGES * SZA;

    int tid = threadIdx.x;
    int wid = tid >> 5, lane = tid & 31;
    int wm = wid & 1, wn = wid >> 1;
    int rowBase = blockIdx.y * 128;
    int colBase = blockIdx.x * 128;

    float c[4][8][4];
#pragma unroll
    for (int mf = 0; mf < 4; mf++)
#pragma unroll
        for (int nf = 0; nf < 8; nf++)
#pragma unroll
            for (int q = 0; q < 4; q++) c[mf][nf][q] = 0.f;

    auto load_chunk = [&](int buf, int ch) {
        int k0 = ch * 32;
#pragma unroll
        for (int i = 0; i < 4; i++) {
            int idx = tid + i * 128;
            int r = idx >> 2, cs = idx & 3;
            int grow = rowBase + r;
            int srow = grow < M ? grow : M - 1;
            cp16(sA + buf * SZA + r * A_PITCH + cs * 16,
                 A + (size_t)srow * KDIM + k0 + cs * 8,
                 grow < M ? 16u : 0u);
        }
#pragma unroll
        for (int i = 0; i < 4; i++) {
            int idx = tid + i * 128;
            int r = idx >> 4, cs = idx & 15;
            cp16(sB + buf * SZB + r * B_PITCH + cs * 16,
                 Bp + (size_t)(k0 + r) * N + colBase + cs * 8, 16u);
        }
        cp_commit();
    };

    uint32_t aAddr = sA + (wm * 64 + (lane & 15)) * A_PITCH + (lane >> 4) * 16;
    uint32_t bAddr = sB + (lane & 15) * B_PITCH + wn * 128 + (lane >> 4) * 16;

    // prologue: fill 3 of 4 stages
    load_chunk(0, 0);
    load_chunk(1, 1);
    if (NCH > 2) load_chunk(2, 2);

    for (int ch = 0; ch < NCH; ch++) {
        int buf = ch % STAGES;
        if (ch >= NCH - 2) cp_wait<0>();
        else               cp_wait<2>();
        __syncthreads();
        if (ch + 3 < NCH) load_chunk((ch + 3) % STAGES, ch + 3);

        uint32_t aB = aAddr + buf * SZA;
        uint32_t bB = bAddr + buf * SZB;
#pragma unroll
        for (int kk = 0; kk < 2; kk++) {
            uint32_t a[16];
#pragma unroll
            for (int g = 0; g < 4; g++)
                LDSM_X4(a[4 * g], a[4 * g + 1], a[4 * g + 2], a[4 * g + 3],
                        aB + g * 16 * A_PITCH + kk * 32);
            uint32_t b[16];
#pragma unroll
            for (int p = 0; p < 4; p++)
                LDSM_X4_T(b[4 * p], b[4 * p + 1], b[4 * p + 2], b[4 * p + 3],
                          bB + kk * 16 * B_PITCH + p * 32);
#pragma unroll
            for (int mf = 0; mf < 4; mf++)
#pragma unroll
                for (int nf = 0; nf < 8; nf++) {
                    uint32_t* bp = b + (nf >> 1) * 4 + (nf & 1) * 2;
                    MMA16816(c[mf][nf], a[4 * mf], a[4 * mf + 1],
                             a[4 * mf + 2], a[4 * mf + 3], bp[0], bp[1]);
                }
        }
    }

    int groupID = lane >> 2, tid4 = lane & 3;
#pragma unroll
    for (int mf = 0; mf < 4; mf++) {
        int r0 = rowBase + wm * 64 + mf * 16 + groupID;
#pragma unroll
        for (int nf = 0; nf < 8; nf++) {
            int cb = colBase + wn * 64 + nf * 8 + tid4 * 2;
            float b0 = 0.f, b1 = 0.f;
            if (MODE != 0) { b0 = bias[cb]; b1 = bias[cb + 1]; }
#pragma unroll
            for (int hh = 0; hh < 2; hh++) {
                int r = r0 + hh * 8;
                if (r >= M) continue;
                float v0 = c[mf][nf][2 * hh + 0] + b0;
                float v1 = c[mf][nf][2 * hh + 1] + b1;
                if (MODE == 0) {
                    __half2 pv;
                    pv.x = __float2half(v0);
                    pv.y = __float2half(v1);
                    *reinterpret_cast<__half2*>(oH + (size_t)r * N + cb) = pv;
                } else if (MODE == 1) {
                    __half2 pv = *reinterpret_cast<const __half2*>(
                        Pin + (size_t)r * N + cb);
                    v0 += __half2float(pv.x);
                    v1 += __half2float(pv.y);
                    v0 = fmaxf(v0, 0.f);
                    v1 = fmaxf(v1, 0.f);
                    *reinterpret_cast<float2*>(C + (size_t)r * N + cb) =
                        make_float2(v0, v1);
                    __half2 hv;
                    hv.x = __float2half(v0);
                    hv.y = __float2half(v1);
                    *reinterpret_cast<__half2*>(oH + (size_t)r * N + cb) = hv;
                } else {
                    *reinterpret_cast<float2*>(C + (size_t)r * N + cb) =
                        make_float2(v0, v1);
                }
            }
        }
    }
}

// ------------------------------ launch -------------------------------------
extern "C" void kernel_launch(void* const* d_in, const int* in_sizes, int n_in,
                              void* d_out, int out_size) {
    const float* x       = (const float*)d_in[0];
    const int*   src     = (const int*)d_in[1];
    const int*   dst     = (const int*)d_in[2];
    const float* W_self  = (const float*)d_in[3];
    const float* W_neigh = (const float*)d_in[4];
    const float* b_enc   = (const float*)d_in[5];
    const float* W_dec   = (const float*)d_in[6];
    const float* b_dec   = (const float*)d_in[7];

    int M  = in_sizes[0] / IN_DIM;
    int nE = in_sizes[1];

    float* out = (float*)d_out;
    float* h;
    if (out_size == M * (OUT_DIM + HID_DIM)) {
        h = out + (long long)M * OUT_DIM;
    } else {
        void* p = nullptr;
        cudaGetSymbolAddress(&p, g_hfb);
        h = (float*)p;
    }

    void *p_eA, *p_hf, *p_P, *p_be, *p_bd, *p_cnt;
    cudaGetSymbolAddress(&p_eA, g_eA);
    cudaGetSymbolAddress(&p_hf, g_hf);
    cudaGetSymbolAddress(&p_P, g_P);
    cudaGetSymbolAddress(&p_be, g_Benc);
    cudaGetSymbolAddress(&p_bd, g_Bdec);
    cudaGetSymbolAddress(&p_cnt, g_cnt);

    cudaFuncSetAttribute(gemm_mma<8, 0>,
                         cudaFuncAttributeMaxDynamicSharedMemorySize, SMEM_DYN);
    cudaFuncSetAttribute(gemm_mma<8, 1>,
                         cudaFuncAttributeMaxDynamicSharedMemorySize, SMEM_DYN);
    cudaFuncSetAttribute(gemm_mma<16, 2>,
                         cudaFuncAttributeMaxDynamicSharedMemorySize, SMEM_DYN);

    static cudaStream_t sA = nullptr;
    static cudaEvent_t ev0 = nullptr, evP = nullptr, evA = nullptr;
    if (!sA) {
        cudaStreamCreateWithFlags(&sA, cudaStreamNonBlocking);
        cudaEventCreateWithFlags(&ev0, cudaEventDisableTiming);
        cudaEventCreateWithFlags(&evP, cudaEventDisableTiming);
        cudaEventCreateWithFlags(&evA, cudaEventDisableTiming);
    }

    // ---- fork: streamA = index chain ----
    cudaEventRecord(ev0, 0);
    cudaStreamWaitEvent(sA, ev0, 0);
    cudaMemsetAsync(p_cnt, 0, (size_t)M * sizeof(int), sA);
    hist_kernel<<<(nE + 255) / 256, 256, 0, sA>>>(dst, nE);
    scan_kernel<<<1, 1024, 0, sA>>>(M);
    sortidx_kernel<<<(nE + 255) / 256, 256, 0, sA>>>(src, dst, nE);

    // ---- stream 0: prep (vectorized) ----
    {
        int total = M * (IN_DIM / 4) + (KDIM * HID_DIM) / 4 + (KDIM * OUT_DIM) / 4;
        prep0_kernel<<<(total + 255) / 256, 256>>>(x, W_self, W_neigh, W_dec, M);
    }
    cudaEventRecord(evP, 0);
    cudaStreamWaitEvent(sA, evP, 0);

    // ---- streamA: aggregate (needs index chain + prep0's x part) ----
    aggregate_kernel<<<(M + 15) / 16, 512, 0, sA>>>(M);
    cudaEventRecord(evA, sA);

    // ---- stream 0 (concurrent with aggregate): x-part GEMM -> fp16 P ----
    {
        dim3 grid(HID_DIM / 128, (M + 127) / 128);
        gemm_mma<8, 0><<<grid, 128, SMEM_DYN>>>(
            (const __half*)p_eA, (const __half*)p_be, nullptr, nullptr,
            nullptr, (__half*)p_P, M, HID_DIM);
    }

    // ---- join: n-part GEMM (reads P), then decoder ----
    cudaStreamWaitEvent(0, evA, 0);
    {
        dim3 grid(HID_DIM / 128, (M + 127) / 128);
        gemm_mma<8, 1><<<grid, 128, SMEM_DYN>>>(
            (const __half*)p_eA + 256,
            (const __half*)p_be + (size_t)256 * HID_DIM,
            b_enc, (const __half*)p_P, h, (__half*)p_hf, M, HID_DIM);
    }
    {
        dim3 grid(OUT_DIM / 128, (M + 127) / 128);
        gemm_mma<16, 2><<<grid, 128, SMEM_DYN>>>(
            (const __half*)p_hf, (const __half*)p_bd, b_dec, nullptr,
            out, nullptr, M, OUT_DIM);
    }
}